// round 8
// baseline (speedup 1.0000x reference)
#include <cuda_runtime.h>

// CfC / liquid-net recurrent cell. 4 threads per pixel (same warp), packed
// f32x2 math. Shapes: B=4, C=16, T=32, H=64, W=64 -> 16384 pixels;
// UNITS=32, BACKBONE=64. ts == 1.0 so Wt = Wta+Wtb, bt = bta+btb.
//
// Lane layout: lane = 4*pix + j (8 pixels/warp, j = 0..3).
//   lane j: backbone rows k in {j, j+4, ..., j+60}; head units [8j, 8j+8).
// h exchanged via warp shuffles; zk via padded smem + __syncwarp only.

#define CC   16
#define TT   32
#define UU   32
#define BKB  64
#define HWSZ 4096
#define NBLOCKS 148
#define WPB 14
#define NTHREADS (WPB * 32)        // 448
#define ACTIVE_WARPS 2048          // 16384 px / 8 px-per-warp

#define ZK_STRIDE 116              // u64 per backbone row (112 px + pad)
#define WBX_STRIDE 20              // floats per backbone row, x part (16 + pad)
#define WBH_STRIDE 36              // floats per backbone row, h part (32 + pad)

#define ZK_U64 (BKB * ZK_STRIDE)   // 7424 u64 = 59392 B
#define OFF_WBX 0
#define OFF_WBH (OFF_WBX + BKB * WBX_STRIDE)   // 1280
#define OFF_W1  (OFF_WBH + BKB * WBH_STRIDE)   // 3584
#define OFF_W2  (OFF_W1 + BKB * UU)            // 5632
#define OFF_WT  (OFF_W2 + BKB * UU)            // 7680
#define OFF_BB  (OFF_WT + BKB * UU)            // 9728
#define OFF_B1  (OFF_BB + BKB)                 // 9792
#define OFF_B2  (OFF_B1 + UU)                  // 9824
#define OFF_BT  (OFF_B2 + UU)                  // 9856
#define F_FLOATS (OFF_BT + UU)                 // 9888
#define SMEM_BYTES (ZK_U64 * 8 + F_FLOATS * 4) // 98944

typedef unsigned long long u64;

__device__ __forceinline__ void ffma2(u64& d, u64 a, u64 b) {
    asm("fma.rn.f32x2 %0, %1, %2, %0;" : "+l"(d) : "l"(a), "l"(b));
}
__device__ __forceinline__ u64 fadd2(u64 a, u64 b) {
    u64 d; asm("add.rn.f32x2 %0, %1, %2;" : "=l"(d) : "l"(a), "l"(b)); return d;
}
__device__ __forceinline__ u64 pack2(float lo, float hi) {
    u64 d; asm("mov.b64 %0, {%1, %2};" : "=l"(d) : "f"(lo), "f"(hi)); return d;
}
__device__ __forceinline__ void unpack2(u64 v, float& lo, float& hi) {
    asm("mov.b64 {%0, %1}, %2;" : "=f"(lo), "=f"(hi) : "l"(v));
}
__device__ __forceinline__ float fast_tanh(float x) {
    float e = __expf(-2.0f * x);
    return __fdividef(2.0f, e + 1.0f) - 1.0f;
}
__device__ __forceinline__ float fast_sig(float x) {
    return __fdividef(1.0f, 1.0f + __expf(-x));
}

__global__ void __launch_bounds__(NTHREADS, 1)
cfc_scan_kernel(const float* __restrict__ x,
                const float* __restrict__ Wb,  const float* __restrict__ bb,
                const float* __restrict__ W1,  const float* __restrict__ b1,
                const float* __restrict__ W2,  const float* __restrict__ b2,
                const float* __restrict__ Wta, const float* __restrict__ bta,
                const float* __restrict__ Wtb, const float* __restrict__ btb,
                float* __restrict__ out)
{
    extern __shared__ u64 smq[];
    u64*   s_zk = smq;
    float* s_f  = (float*)(smq + ZK_U64);

    const int tid = threadIdx.x;

    // ---- stage weights (padded layouts) ----
    for (int i = tid; i < BKB * 48; i += NTHREADS) {
        int k = i / 48, c = i % 48;
        float v = Wb[i];
        if (c < 16) s_f[OFF_WBX + k * WBX_STRIDE + c] = v;
        else        s_f[OFF_WBH + k * WBH_STRIDE + (c - 16)] = v;
    }
    for (int i = tid; i < UU * BKB; i += NTHREADS) {
        int u = i / BKB, c = i % BKB;           // row-major [u][c] -> c-major [c][u]
        s_f[OFF_W1 + c * UU + u] = W1[i];
        s_f[OFF_W2 + c * UU + u] = W2[i];
        s_f[OFF_WT + c * UU + u] = Wta[i] + Wtb[i];
    }
    if (tid < BKB) s_f[OFF_BB + tid] = bb[tid];
    if (tid < UU) {
        s_f[OFF_B1 + tid] = b1[tid];
        s_f[OFF_B2 + tid] = b2[tid];
        s_f[OFF_BT + tid] = bta[tid] + btb[tid];
    }
    __syncthreads();

    const int wib  = tid >> 5;                 // warp in block
    const int lane = tid & 31;
    const int W    = blockIdx.x * WPB + wib;   // global warp id
    if (W >= ACTIVE_WARPS) return;             // no block-level syncs below

    const int pix = lane >> 2;                 // pixel within warp (0..7)
    const int j   = lane & 3;                  // cooperating thread (0..3)
    const int p   = W * 8 + pix;               // global pixel 0..16383
    const int b   = p >> 12;
    const int hw  = p & 4095;
    const int px_local = wib * 8 + pix;        // 0..111

    const float* xb = x   + ((size_t)b * CC) * (TT * HWSZ) + hw;   // x[b,c,t,hw]
    float*       ob = out + ((size_t)b * UU) * (TT * HWSZ) + hw;   // out[b,u,t,hw]

    u64* zk_rd = s_zk + px_local;              // read: zk_rd[c*ZK_STRIDE]

    u64 hp_own[4];                             // units 8j..8j+7 (packed pairs)
#pragma unroll
    for (int m = 0; m < 4; m++) hp_own[m] = 0ull;

    for (int t = 0; t < TT; t++) {
        // ---- load + pack this step's x channels ----
        float xv[CC];
#pragma unroll
        for (int c = 0; c < CC; c++) xv[c] = xb[(c * TT + t) * HWSZ];
        u64 xp[CC / 2];
#pragma unroll
        for (int m = 0; m < CC / 2; m++) xp[m] = pack2(xv[2 * m], xv[2 * m + 1]);

        // ---- gather full h (32 vals = 16 packed) from the 4 pixel lanes ----
        u64 hfull[16];
#pragma unroll
        for (int q = 0; q < 16; q++)
            hfull[q] = __shfl_sync(0xFFFFFFFFu, hp_own[q & 3],
                                   (lane & ~3) | (q >> 2));

        __syncwarp();   // prior-step head reads done before zk overwrite

        // ---- backbone: rows k = 4i + j ----
#pragma unroll 4
        for (int i = 0; i < 16; i++) {
            const int k = 4 * i + j;
            const ulonglong2* wx = (const ulonglong2*)(s_f + OFF_WBX + k * WBX_STRIDE);
            const ulonglong2* wh = (const ulonglong2*)(s_f + OFF_WBH + k * WBH_STRIDE);
            u64 a0 = 0ull, a1 = 0ull, a2 = 0ull, a3 = 0ull;
#pragma unroll
            for (int m = 0; m < 4; m++) {
                ulonglong2 w = wx[m];
                ffma2(a0, w.x, xp[2 * m]);
                ffma2(a1, w.y, xp[2 * m + 1]);
            }
#pragma unroll
            for (int m = 0; m < 4; m++) {
                ulonglong2 w0 = wh[2 * m];
                ulonglong2 w1 = wh[2 * m + 1];
                ffma2(a2, w0.x, hfull[4 * m]);
                ffma2(a3, w0.y, hfull[4 * m + 1]);
                ffma2(a0, w1.x, hfull[4 * m + 2]);
                ffma2(a1, w1.y, hfull[4 * m + 3]);
            }
            u64 s = fadd2(fadd2(a0, a1), fadd2(a2, a3));
            float lo, hi; unpack2(s, lo, hi);
            float acc = lo + hi + s_f[OFF_BB + k];
            float z = 1.7159f * fast_tanh(0.666f * acc);
            s_zk[k * ZK_STRIDE + px_local] = pack2(z, z);   // duplicated-packed
        }

        __syncwarp();   // zk(t) visible to all 4 lanes of the pixel

        // ---- heads: this lane's 8 units, all three heads fused ----
        u64 A1[4], A2[4], AT[4];
#pragma unroll
        for (int m = 0; m < 4; m++) { A1[m] = 0ull; A2[m] = 0ull; AT[m] = 0ull; }
#pragma unroll 4
        for (int c = 0; c < BKB; c++) {
            u64 qq = zk_rd[c * ZK_STRIDE];                   // (z, z)
            const ulonglong2* w1p = (const ulonglong2*)(s_f + OFF_W1 + c * UU + 8 * j);
            const ulonglong2* w2p = (const ulonglong2*)(s_f + OFF_W2 + c * UU + 8 * j);
            const ulonglong2* wtp = (const ulonglong2*)(s_f + OFF_WT + c * UU + 8 * j);
            ulonglong2 w1a = w1p[0], w1b = w1p[1];
            ffma2(A1[0], w1a.x, qq); ffma2(A1[1], w1a.y, qq);
            ffma2(A1[2], w1b.x, qq); ffma2(A1[3], w1b.y, qq);
            ulonglong2 w2a = w2p[0], w2b = w2p[1];
            ffma2(A2[0], w2a.x, qq); ffma2(A2[1], w2a.y, qq);
            ffma2(A2[2], w2b.x, qq); ffma2(A2[3], w2b.y, qq);
            ulonglong2 wta = wtp[0], wtb = wtp[1];
            ffma2(AT[0], wta.x, qq); ffma2(AT[1], wta.y, qq);
            ffma2(AT[2], wtb.x, qq); ffma2(AT[3], wtb.y, qq);
        }
#pragma unroll
        for (int m = 0; m < 4; m++) {
            const int u = 8 * j + 2 * m;
            float p0, p1, q0, q1, r0, r1;
            unpack2(A1[m], p0, p1);
            unpack2(A2[m], q0, q1);
            unpack2(AT[m], r0, r1);
            float f10 = fast_tanh(p0 + s_f[OFF_B1 + u]);
            float f11 = fast_tanh(p1 + s_f[OFF_B1 + u + 1]);
            float f20 = fast_tanh(q0 + s_f[OFF_B2 + u]);
            float f21 = fast_tanh(q1 + s_f[OFF_B2 + u + 1]);
            float ti0 = fast_sig(r0 + s_f[OFF_BT + u]);
            float ti1 = fast_sig(r1 + s_f[OFF_BT + u + 1]);
            float h0 = f10 + ti0 * (f20 - f10);   // ff1*(1-ti) + ti*ff2
            float h1 = f11 + ti1 * (f21 - f11);
            hp_own[m] = pack2(h0, h1);
            ob[((u) * TT + t) * HWSZ]     = h0;   // out[b,u,t,hw]
            ob[((u + 1) * TT + t) * HWSZ] = h1;
        }
    }
}

extern "C" void kernel_launch(void* const* d_in, const int* in_sizes, int n_in,
                              void* d_out, int out_size)
{
    const float* x   = (const float*)d_in[0];
    const float* Wb  = (const float*)d_in[1];
    const float* bb  = (const float*)d_in[2];
    const float* W1  = (const float*)d_in[3];
    const float* b1  = (const float*)d_in[4];
    const float* W2  = (const float*)d_in[5];
    const float* b2  = (const float*)d_in[6];
    const float* Wta = (const float*)d_in[7];
    const float* bta = (const float*)d_in[8];
    const float* Wtb = (const float*)d_in[9];
    const float* btb = (const float*)d_in[10];
    float* out = (float*)d_out;

    cudaFuncSetAttribute(cfc_scan_kernel,
                         cudaFuncAttributeMaxDynamicSharedMemorySize, SMEM_BYTES);

    cfc_scan_kernel<<<NBLOCKS, NTHREADS, SMEM_BYTES>>>(
        x, Wb, bb, W1, b1, W2, b2, Wta, bta, Wtb, btb, out);
}